// round 15
// baseline (speedup 1.0000x reference)
#include <cuda_runtime.h>
#include <math.h>

#define Nn 1024
#define Vv 3889
#define NJj 33
#define NBb 41
#define M3 11667   // V*3
#define JRW 3904   // padded row width for transposed J_regressor

// ---------------- scratch (static device allocations) ----------------------
__device__ float g_vshaped[Nn * M3];          // ~48 MB
__device__ __align__(16) float g_A2f[512 * 396 * 2]; // A packed per body-pair (f32x2 lanes)
__device__ float g_SJ[NBb * 99];              // shapedirs folded through J_regressor
__device__ float g_Jt[99];                    // template joints
__device__ float g_jrT[NJj * JRW];            // J_regressor transposed [j][v]
__device__ float g_jpart[Nn * 32 * 99];       // per-(chunk,half) joint partials

// scal code per (joint, axis): 0 -> 1.0, 1..4 -> exp(betas_logscale[c-1])
__constant__ unsigned char c_sc[99] = {
    0,0,0, 0,0,0, 0,0,0, 0,0,0, 0,0,0, 0,0,0, 0,0,0,
    2,2,1, 2,2,1, 2,2,1, 2,2,1, 2,2,1, 2,2,1, 2,2,1, 2,2,1,
    0,0,0, 0,0,0,
    2,2,1, 2,2,1, 2,2,1, 2,2,1, 2,2,1, 2,2,1, 2,2,1, 2,2,1,
    3,4,4, 3,4,4, 3,4,4, 3,4,4, 3,4,4, 3,4,4, 3,4,4,
    0,0,0
};

// ---------------- packed f32x2 helpers -------------------------------------
typedef unsigned long long u64;
__device__ __forceinline__ u64 pk2(float a, float b) {
    u64 r; asm("mov.b64 %0,{%1,%2};" : "=l"(r) : "f"(a), "f"(b)); return r;
}
__device__ __forceinline__ void upk2(u64 v, float& a, float& b) {
    asm("mov.b64 {%0,%1},%2;" : "=f"(a), "=f"(b) : "l"(v));
}
__device__ __forceinline__ u64 fma2(u64 a, u64 b, u64 c) {
    u64 r; asm("fma.rn.f32x2 %0,%1,%2,%3;" : "=l"(r) : "l"(a), "l"(b), "l"(c)); return r;
}
__device__ __forceinline__ u64 add2(u64 a, u64 b) {
    u64 r; asm("add.rn.f32x2 %0,%1,%2;" : "=l"(r) : "l"(a), "l"(b)); return r;
}

// ---------------- K0: transpose J_regressor --------------------------------
__global__ void k_jrT(const float* __restrict__ jr) {
    int j = blockIdx.y;
    int v = blockIdx.x * 256 + threadIdx.x;
    if (v < Vv) g_jrT[j * JRW + v] = jr[v * NJj + j];
}

// ---------------- K1: fold shapedirs / v_template through J_regressor ------
__global__ void __launch_bounds__(256) k_sj(const float* __restrict__ sd,
                                            const float* __restrict__ vt) {
    int k = blockIdx.x, j = blockIdx.y;
    const float* src = (k < NBb) ? (sd + k * M3) : vt;
    const float* jrow = g_jrT + j * JRW;
    float a0 = 0.f, a1 = 0.f, a2 = 0.f;
    for (int v = threadIdx.x; v < Vv; v += 256) {
        float w = jrow[v];
        a0 = fmaf(w, src[v * 3 + 0], a0);
        a1 = fmaf(w, src[v * 3 + 1], a1);
        a2 = fmaf(w, src[v * 3 + 2], a2);
    }
    #pragma unroll
    for (int off = 16; off; off >>= 1) {
        a0 += __shfl_down_sync(0xffffffffu, a0, off);
        a1 += __shfl_down_sync(0xffffffffu, a1, off);
        a2 += __shfl_down_sync(0xffffffffu, a2, off);
    }
    __shared__ float r0[8], r1[8], r2[8];
    int wid = threadIdx.x >> 5, lane = threadIdx.x & 31;
    if (lane == 0) { r0[wid] = a0; r1[wid] = a1; r2[wid] = a2; }
    __syncthreads();
    if (threadIdx.x == 0) {
        a0 = a1 = a2 = 0.f;
        #pragma unroll
        for (int w = 0; w < 8; w++) { a0 += r0[w]; a1 += r1[w]; a2 += r2[w]; }
        float* dst = (k < NBb) ? (g_SJ + k * 99 + j * 3) : (g_Jt + j * 3);
        dst[0] = a0; dst[1] = a1; dst[2] = a2;
    }
}

// ---------------- K2: v_shaped; sd staged in smem (R10-measured-best) ------
__global__ void __launch_bounds__(256) k_vshape(const float* __restrict__ beta,
                                                const float* __restrict__ sd,
                                                const float* __restrict__ vt) {
    __shared__ __align__(16) float sds[NBb * 256];   // 41984 B
    __shared__ __align__(16) u64 bs2[NBb * 16];      // 5248 B
    int n0 = blockIdx.y * 32;
    int m0blk = blockIdx.x * 256;
    int tx = threadIdx.x;
    for (int i = tx; i < NBb * 16; i += 256) {
        int k = i >> 4, p = i & 15;
        bs2[i] = pk2(beta[(n0 + 2 * p) * NBb + k], beta[(n0 + 2 * p + 1) * NBb + k]);
    }
    {
        int cnt = min(256, M3 - m0blk);
        #pragma unroll 8
        for (int k = 0; k < NBb; k++)
            sds[k * 256 + tx] = (tx < cnt) ? sd[k * M3 + m0blk + tx] : 0.f;
    }
    __syncthreads();
    int m = m0blk + tx;
    if (m >= M3) return;
    float base = vt[m];
    u64 acc[16];
    u64 b0 = pk2(base, base);
    #pragma unroll
    for (int p = 0; p < 16; p++) acc[p] = b0;
    #pragma unroll 2
    for (int k = 0; k < NBb; k++) {
        float s = sds[k * 256 + tx];
        u64 sp = pk2(s, s);
        const ulonglong2* row = (const ulonglong2*)(bs2 + k * 16);
        #pragma unroll
        for (int h = 0; h < 8; h++) {
            ulonglong2 e = row[h];
            acc[2 * h + 0] = fma2(e.x, sp, acc[2 * h + 0]);
            acc[2 * h + 1] = fma2(e.y, sp, acc[2 * h + 1]);
        }
    }
    #pragma unroll
    for (int p = 0; p < 16; p++) {
        float lo, hi;
        upk2(acc[p], lo, hi);
        g_vshaped[(size_t)(n0 + 2 * p) * M3 + m] = lo;
        g_vshaped[(size_t)(n0 + 2 * p + 1) * M3 + m] = hi;
    }
}

// ---------------- K3: locals + chain compose; SJ/Jt staged in smem ---------
__device__ __forceinline__ void rodrigues(float t0, float t1, float t2, float R[9]) {
    float a0 = t0 + 1e-8f, a1 = t1 + 1e-8f, a2 = t2 + 1e-8f;
    float ang = sqrtf(a0 * a0 + a1 * a1 + a2 * a2);
    float inv = 1.f / ang;
    float r0 = t0 * inv, r1 = t1 * inv, r2 = t2 * inv;
    float s, c;
    sincosf(ang, &s, &c);
    float oc = 1.f - c;
    R[0] = c + oc * r0 * r0;       R[1] = oc * r0 * r1 - s * r2;  R[2] = oc * r0 * r2 + s * r1;
    R[3] = oc * r0 * r1 + s * r2;  R[4] = c + oc * r1 * r1;       R[5] = oc * r1 * r2 - s * r0;
    R[6] = oc * r0 * r2 - s * r1;  R[7] = oc * r1 * r2 + s * r0;  R[8] = c + oc * r2 * r2;
}

__global__ void __launch_bounds__(288) k_lc(const float* __restrict__ beta,
                                            const float* __restrict__ theta,
                                            const float* __restrict__ bls) {
    __shared__ float sL[8 * 396];
    __shared__ float sJ[8 * 99];
    __shared__ float sSJ[NBb * 99];   // 16236 B
    __shared__ float sJt[99];
    int n0 = blockIdx.x * 8;
    int tx = threadIdx.x;
    for (int i = tx; i < NBb * 99; i += 288) sSJ[i] = g_SJ[i];
    if (tx < 99) sJt[tx] = g_Jt[tx];
    __syncthreads();
    if (tx < 264) {
        int b = tx / 33, i = tx - b * 33;
        int n = n0 + b;
        const float* bt = beta + n * NBb;
        float e[5];
        e[0] = 1.f;
        e[1] = expf(bls[n * 6 + 0]);
        e[2] = expf(bls[n * 6 + 1]);
        e[3] = expf(bls[n * 6 + 2]);
        e[4] = expf(bls[n * 6 + 3]);

        float Ji[3] = {sJt[i * 3 + 0], sJt[i * 3 + 1], sJt[i * 3 + 2]};
        #pragma unroll
        for (int k = 0; k < NBb; k++) {
            const float* s = sSJ + k * 99 + i * 3;
            float bk = bt[k];
            Ji[0] = fmaf(bk, s[0], Ji[0]);
            Ji[1] = fmaf(bk, s[1], Ji[1]);
            Ji[2] = fmaf(bk, s[2], Ji[2]);
        }
        sJ[b * 99 + i * 3 + 0] = Ji[0];
        sJ[b * 99 + i * 3 + 1] = Ji[1];
        sJ[b * 99 + i * 3 + 2] = Ji[2];

        float R[9];
        rodrigues(theta[n * 105 + i * 3 + 0], theta[n * 105 + i * 3 + 1],
                  theta[n * 105 + i * 3 + 2], R);
        float* L = sL + b * 396 + i * 12;
        if (i == 0) {
            #pragma unroll
            for (int r = 0; r < 3; r++) {
                L[r * 4 + 0] = R[r * 3 + 0];
                L[r * 4 + 1] = R[r * 3 + 1];
                L[r * 4 + 2] = R[r * 3 + 2];
                L[r * 4 + 3] = Ji[r];
            }
        } else {
            int p = i - 1;
            float Jp[3] = {sJt[p * 3 + 0], sJt[p * 3 + 1], sJt[p * 3 + 2]};
            #pragma unroll
            for (int k = 0; k < NBb; k++) {
                const float* s = sSJ + k * 99 + p * 3;
                float bk = bt[k];
                Jp[0] = fmaf(bk, s[0], Jp[0]);
                Jp[1] = fmaf(bk, s[1], Jp[1]);
                Jp[2] = fmaf(bk, s[2], Jp[2]);
            }
            float sic[3] = {e[c_sc[i * 3 + 0]], e[c_sc[i * 3 + 1]], e[c_sc[i * 3 + 2]]};
            float ipr[3] = {1.f / e[c_sc[p * 3 + 0]], 1.f / e[c_sc[p * 3 + 1]],
                            1.f / e[c_sc[p * 3 + 2]]};
            #pragma unroll
            for (int r = 0; r < 3; r++) {
                #pragma unroll
                for (int c = 0; c < 3; c++)
                    L[r * 4 + c] = R[r * 3 + c] * sic[c] * ipr[r];
                L[r * 4 + 3] = Ji[r] - Jp[r];
            }
        }
    }
    __syncthreads();
    // chain compose: 3 independent G-rows per body -> 24 active threads
    if (tx < 24) {
        int b = tx / 3, r = tx - b * 3;
        int n = n0 + b;
        int pr = n >> 1, lane = n & 1;
        float* out = g_A2f + (size_t)pr * 792 + lane;
        const float* Lb = sL + b * 396;
        const float* Jb = sJ + b * 99;
        float G[4];
        #pragma unroll
        for (int c = 0; c < 4; c++) G[c] = Lb[r * 4 + c];
        #pragma unroll 1
        for (int i = 0; i < NJj; i++) {
            if (i > 0) {
                const float* L = Lb + i * 12;
                float Gn[4];
                #pragma unroll
                for (int c = 0; c < 4; c++) {
                    float acc = (c == 3) ? G[3] : 0.f;
                    acc = fmaf(G[0], L[0 * 4 + c], acc);
                    acc = fmaf(G[1], L[1 * 4 + c], acc);
                    acc = fmaf(G[2], L[2 * 4 + c], acc);
                    Gn[c] = acc;
                }
                #pragma unroll
                for (int c = 0; c < 4; c++) G[c] = Gn[c];
            }
            float ib = G[0] * Jb[i * 3 + 0] + G[1] * Jb[i * 3 + 1] + G[2] * Jb[i * 3 + 2];
            out[(i * 12 + r * 4 + 0) * 2] = G[0];
            out[(i * 12 + r * 4 + 1) * 2] = G[1];
            out[(i * 12 + r * 4 + 2) * 2] = G[2];
            out[(i * 12 + r * 4 + 3) * 2] = G[3] - ib;
        }
    }
}

// ---------------- K4: skinning; 128 thr, 2 verts/thread, 16 bodies/block ---
__device__ __forceinline__ int eidx(int v) {
    if (v == 1863) return 0;
    if (v == 26)   return 1;
    if (v == 2124) return 2;
    if (v == 150)  return 3;
    if (v == 3055) return 4;
    if (v == 1097) return 5;
    return -1;
}

__global__ void __launch_bounds__(128) k_skin(const float* __restrict__ wts,
                                              const float* __restrict__ trans,
                                              float* __restrict__ outv,
                                              float* __restrict__ outj) {
    __shared__ __align__(16) float sw[256 * 33];
    __shared__ __align__(16) u64 As2[396];
    int chunk = blockIdx.x, n0 = blockIdx.y * 16;
    int v0 = chunk * 256;
    int tx = threadIdx.x;
    int cnt = min(256, Vv - v0);
    int wtot = cnt * 33;
    const u64* gA2 = (const u64*)g_A2f;
    for (int i = tx; i < 8448; i += 128) sw[i] = (i < wtot) ? wts[v0 * 33 + i] : 0.f;
    int va = v0 + tx, vb = va + 128;
    bool ga = tx < cnt, gb = tx + 128 < cnt;
    int ea = eidx(va), eb = eidx(vb);

    #pragma unroll 1
    for (int pair = 0; pair < 8; pair++) {
        int pr = (n0 >> 1) + pair;
        int b0 = 2 * pr, b1 = b0 + 1;
        __syncthreads();
        for (int i = tx; i < 396; i += 128) As2[i] = gA2[(size_t)pr * 396 + i];
        __syncthreads();

        u64 vax = 0, vay = 0, vaz = 0, vbx = 0, vby = 0, vbz = 0;
        if (ga) {
            const float* q0 = g_vshaped + (size_t)b0 * M3 + va * 3;
            const float* q1 = g_vshaped + (size_t)b1 * M3 + va * 3;
            vax = pk2(q0[0], q1[0]); vay = pk2(q0[1], q1[1]); vaz = pk2(q0[2], q1[2]);
        }
        if (gb) {
            const float* q0 = g_vshaped + (size_t)b0 * M3 + vb * 3;
            const float* q1 = g_vshaped + (size_t)b1 * M3 + vb * 3;
            vbx = pk2(q0[0], q1[0]); vby = pk2(q0[1], q1[1]); vbz = pk2(q0[2], q1[2]);
        }
        u64 accA[12], accB[12];
        #pragma unroll
        for (int q = 0; q < 12; q++) { accA[q] = 0ull; accB[q] = 0ull; }
        const ulonglong2* Ap = (const ulonglong2*)As2;
        #pragma unroll 3
        for (int j = 0; j < 33; j++) {
            float wa = sw[tx * 33 + j];
            float wb = sw[(tx + 128) * 33 + j];
            u64 wa2 = pk2(wa, wa), wb2 = pk2(wb, wb);
            #pragma unroll
            for (int r = 0; r < 3; r++) {
                ulonglong2 e0 = Ap[j * 6 + r * 2 + 0];
                ulonglong2 e1 = Ap[j * 6 + r * 2 + 1];
                accA[r * 4 + 0] = fma2(wa2, e0.x, accA[r * 4 + 0]);
                accA[r * 4 + 1] = fma2(wa2, e0.y, accA[r * 4 + 1]);
                accA[r * 4 + 2] = fma2(wa2, e1.x, accA[r * 4 + 2]);
                accA[r * 4 + 3] = fma2(wa2, e1.y, accA[r * 4 + 3]);
                accB[r * 4 + 0] = fma2(wb2, e0.x, accB[r * 4 + 0]);
                accB[r * 4 + 1] = fma2(wb2, e0.y, accB[r * 4 + 1]);
                accB[r * 4 + 2] = fma2(wb2, e1.x, accB[r * 4 + 2]);
                accB[r * 4 + 3] = fma2(wb2, e1.y, accB[r * 4 + 3]);
            }
        }
        u64 tr2[3];
        #pragma unroll
        for (int r = 0; r < 3; r++) tr2[r] = pk2(trans[b0 * 3 + r], trans[b1 * 3 + r]);
        #pragma unroll
        for (int r = 0; r < 3; r++) {
            u64 oA = fma2(accA[r * 4 + 0], vax,
                     fma2(accA[r * 4 + 1], vay,
                     fma2(accA[r * 4 + 2], vaz, add2(accA[r * 4 + 3], tr2[r]))));
            u64 oB = fma2(accB[r * 4 + 0], vbx,
                     fma2(accB[r * 4 + 1], vby,
                     fma2(accB[r * 4 + 2], vbz, add2(accB[r * 4 + 3], tr2[r]))));
            float lo, hi;
            if (ga) {
                upk2(oA, lo, hi);
                outv[(size_t)b0 * M3 + va * 3 + r] = lo;
                outv[(size_t)b1 * M3 + va * 3 + r] = hi;
                if (ea >= 0) {
                    outj[b0 * 117 + (33 + ea) * 3 + r] = lo;
                    outj[b1 * 117 + (33 + ea) * 3 + r] = hi;
                }
            }
            if (gb) {
                upk2(oB, lo, hi);
                outv[(size_t)b0 * M3 + vb * 3 + r] = lo;
                outv[(size_t)b1 * M3 + vb * 3 + r] = hi;
                if (eb >= 0) {
                    outj[b0 * 117 + (33 + eb) * 3 + r] = lo;
                    outj[b1 * 117 + (33 + eb) * 3 + r] = hi;
                }
            }
        }
    }
}

// ---------------- K5: joint partials; double-buffered, 1 sync/pair ---------
__global__ void __launch_bounds__(256) k_joints(const float* __restrict__ verts) {
    __shared__ __align__(16) float jrTs[NJj * 258];
    __shared__ __align__(16) float vsT[2][6 * 264];
    int chunk = blockIdx.x, n0 = blockIdx.y * 32;
    int v0 = chunk * 256;
    int tx = threadIdx.x;
    int cnt = min(256, Vv - v0);
    for (int i = tx; i < NJj * 256; i += 256) {
        int jj = i >> 8, v = i & 255;
        jrTs[jj * 258 + v] = (v < cnt) ? g_jrT[jj * JRW + v0 + v] : 0.f;
    }
    int g = tx / 99, q2 = tx - g * 99;
    int j = q2 / 3, a = q2 - j * 3;
    bool act = tx < 198;

    // stage pair 0 into buffer 0
    for (int i = tx; i < 1536; i += 256) {
        int b = i / 768, q = i - b * 768;
        int v = q / 3, aa = q - v * 3;
        vsT[0][(b * 3 + aa) * 264 + v] =
            (v < cnt) ? verts[(size_t)(n0 + b) * M3 + v0 * 3 + q] : 0.f;
    }
    __syncthreads();

    #pragma unroll 1
    for (int pair = 0; pair < 16; pair++) {
        int cur = pair & 1;
        if (pair < 15) {
            int b0n = n0 + 2 * (pair + 1);
            for (int i = tx; i < 1536; i += 256) {
                int b = i / 768, q = i - b * 768;
                int v = q / 3, aa = q - v * 3;
                vsT[1 - cur][(b * 3 + aa) * 264 + v] =
                    (v < cnt) ? verts[(size_t)(b0n + b) * M3 + v0 * 3 + q] : 0.f;
            }
        }
        if (act) {
            u64 acc0 = 0ull, acc1 = 0ull;
            const u64* jp = (const u64*)(jrTs + j * 258) + g * 64;
            const u64* p0 = (const u64*)(vsT[cur] + a * 264) + g * 64;
            const u64* p1 = (const u64*)(vsT[cur] + (3 + a) * 264) + g * 64;
            #pragma unroll 8
            for (int h = 0; h < 64; h++) {
                u64 jv = jp[h];
                acc0 = fma2(p0[h], jv, acc0);
                acc1 = fma2(p1[h], jv, acc1);
            }
            int b0 = n0 + 2 * pair;
            float lo, hi;
            upk2(acc0, lo, hi);
            g_jpart[((size_t)b0 * 32 + chunk * 2 + g) * 99 + q2] = lo + hi;
            upk2(acc1, lo, hi);
            g_jpart[((size_t)(b0 + 1) * 32 + chunk * 2 + g) * 99 + q2] = lo + hi;
        }
        __syncthreads();
    }
}

// ---------------- K6: deterministic joint reduce (32 fixed-order partials) -
__global__ void k_jred(float* __restrict__ outj) {
    int idx = blockIdx.x * 256 + threadIdx.x;
    if (idx >= Nn * 99) return;
    int n = idx / 99, t = idx - n * 99;
    const float* p = g_jpart + (size_t)n * 32 * 99 + t;
    float acc = 0.f;
    #pragma unroll
    for (int c = 0; c < 32; c++) acc += p[c * 99];
    outj[n * 117 + t] = acc;
}

// ---------------- launch: fork-join so vshape overlaps jrT->sj->lc ---------
extern "C" void kernel_launch(void* const* d_in, const int* in_sizes, int n_in,
                              void* d_out, int out_size) {
    const float* beta  = (const float*)d_in[0];
    const float* theta = (const float*)d_in[1];
    const float* trans = (const float*)d_in[2];
    const float* bls   = (const float*)d_in[3];
    const float* sd    = (const float*)d_in[4];
    const float* vt    = (const float*)d_in[5];
    const float* jreg  = (const float*)d_in[6];
    // d_in[7] = posedirs: multiplied by exact zeros in the reference -> unused
    const float* wts   = (const float*)d_in[8];
    float* outv = (float*)d_out;
    float* outj = outv + (size_t)Nn * M3;

    cudaStream_t s2;
    cudaStreamCreateWithFlags(&s2, cudaStreamNonBlocking);
    cudaEvent_t eFork, eJoin;
    cudaEventCreateWithFlags(&eFork, cudaEventDisableTiming);
    cudaEventCreateWithFlags(&eJoin, cudaEventDisableTiming);

    // fork: vshape on s2, concurrent with jrT -> sj -> lc on the main stream
    cudaEventRecord(eFork, 0);
    cudaStreamWaitEvent(s2, eFork, 0);
    k_vshape <<<dim3(46, 32), 256, 0, s2>>>(beta, sd, vt);
    cudaEventRecord(eJoin, s2);

    k_jrT    <<<dim3(16, 33), 256>>>(jreg);
    k_sj     <<<dim3(42, 33), 256>>>(sd, vt);
    k_lc     <<<128, 288>>>(beta, theta, bls);

    // join: skin needs both vshape and lc
    cudaStreamWaitEvent(0, eJoin, 0);
    k_skin   <<<dim3(16, 64), 128>>>(wts, trans, outv, outj);
    k_joints <<<dim3(16, 32), 256>>>(outv);
    k_jred   <<<(Nn * 99 + 255) / 256, 256>>>(outj);
}

// round 16
// speedup vs baseline: 1.0137x; 1.0137x over previous
#include <cuda_runtime.h>
#include <math.h>

#define Nn 1024
#define Vv 3889
#define NJj 33
#define NBb 41
#define M3 11667   // V*3
#define JRW 3904   // padded row width for transposed J_regressor

// ---------------- scratch (static device allocations) ----------------------
__device__ float g_vshaped[Nn * M3];          // ~48 MB
__device__ __align__(16) float g_A2f[512 * 396 * 2]; // A packed per body-pair (f32x2 lanes)
__device__ float g_SJ[NBb * 99];              // shapedirs folded through J_regressor
__device__ float g_Jt[99];                    // template joints
__device__ float g_jrT[NJj * JRW];            // J_regressor transposed [j][v]
__device__ float g_jpart[Nn * 32 * 99];       // per-(chunk,half) joint partials

// scal code per (joint, axis): 0 -> 1.0, 1..4 -> exp(betas_logscale[c-1])
__constant__ unsigned char c_sc[99] = {
    0,0,0, 0,0,0, 0,0,0, 0,0,0, 0,0,0, 0,0,0, 0,0,0,
    2,2,1, 2,2,1, 2,2,1, 2,2,1, 2,2,1, 2,2,1, 2,2,1, 2,2,1,
    0,0,0, 0,0,0,
    2,2,1, 2,2,1, 2,2,1, 2,2,1, 2,2,1, 2,2,1, 2,2,1, 2,2,1,
    3,4,4, 3,4,4, 3,4,4, 3,4,4, 3,4,4, 3,4,4, 3,4,4,
    0,0,0
};

// ---------------- packed f32x2 helpers -------------------------------------
typedef unsigned long long u64;
__device__ __forceinline__ u64 pk2(float a, float b) {
    u64 r; asm("mov.b64 %0,{%1,%2};" : "=l"(r) : "f"(a), "f"(b)); return r;
}
__device__ __forceinline__ void upk2(u64 v, float& a, float& b) {
    asm("mov.b64 {%0,%1},%2;" : "=f"(a), "=f"(b) : "l"(v));
}
__device__ __forceinline__ u64 fma2(u64 a, u64 b, u64 c) {
    u64 r; asm("fma.rn.f32x2 %0,%1,%2,%3;" : "=l"(r) : "l"(a), "l"(b), "l"(c)); return r;
}
__device__ __forceinline__ u64 add2(u64 a, u64 b) {
    u64 r; asm("add.rn.f32x2 %0,%1,%2;" : "=l"(r) : "l"(a), "l"(b)); return r;
}

// ---------------- K0: transpose J_regressor --------------------------------
__global__ void k_jrT(const float* __restrict__ jr) {
    int j = blockIdx.y;
    int v = blockIdx.x * 256 + threadIdx.x;
    if (v < Vv) g_jrT[j * JRW + v] = jr[v * NJj + j];
}

// ---------------- K1: fold shapedirs / v_template through J_regressor ------
__global__ void __launch_bounds__(256) k_sj(const float* __restrict__ sd,
                                            const float* __restrict__ vt) {
    int k = blockIdx.x, j = blockIdx.y;
    const float* src = (k < NBb) ? (sd + k * M3) : vt;
    const float* jrow = g_jrT + j * JRW;
    float a0 = 0.f, a1 = 0.f, a2 = 0.f;
    for (int v = threadIdx.x; v < Vv; v += 256) {
        float w = jrow[v];
        a0 = fmaf(w, src[v * 3 + 0], a0);
        a1 = fmaf(w, src[v * 3 + 1], a1);
        a2 = fmaf(w, src[v * 3 + 2], a2);
    }
    #pragma unroll
    for (int off = 16; off; off >>= 1) {
        a0 += __shfl_down_sync(0xffffffffu, a0, off);
        a1 += __shfl_down_sync(0xffffffffu, a1, off);
        a2 += __shfl_down_sync(0xffffffffu, a2, off);
    }
    __shared__ float r0[8], r1[8], r2[8];
    int wid = threadIdx.x >> 5, lane = threadIdx.x & 31;
    if (lane == 0) { r0[wid] = a0; r1[wid] = a1; r2[wid] = a2; }
    __syncthreads();
    if (threadIdx.x == 0) {
        a0 = a1 = a2 = 0.f;
        #pragma unroll
        for (int w = 0; w < 8; w++) { a0 += r0[w]; a1 += r1[w]; a2 += r2[w]; }
        float* dst = (k < NBb) ? (g_SJ + k * 99 + j * 3) : (g_Jt + j * 3);
        dst[0] = a0; dst[1] = a1; dst[2] = a2;
    }
}

// ---------------- K2: v_shaped; sd staged in smem (R10-measured-best) ------
__global__ void __launch_bounds__(256) k_vshape(const float* __restrict__ beta,
                                                const float* __restrict__ sd,
                                                const float* __restrict__ vt) {
    __shared__ __align__(16) float sds[NBb * 256];   // 41984 B
    __shared__ __align__(16) u64 bs2[NBb * 16];      // 5248 B
    int n0 = blockIdx.y * 32;
    int m0blk = blockIdx.x * 256;
    int tx = threadIdx.x;
    for (int i = tx; i < NBb * 16; i += 256) {
        int k = i >> 4, p = i & 15;
        bs2[i] = pk2(beta[(n0 + 2 * p) * NBb + k], beta[(n0 + 2 * p + 1) * NBb + k]);
    }
    {
        int cnt = min(256, M3 - m0blk);
        #pragma unroll 8
        for (int k = 0; k < NBb; k++)
            sds[k * 256 + tx] = (tx < cnt) ? sd[k * M3 + m0blk + tx] : 0.f;
    }
    __syncthreads();
    int m = m0blk + tx;
    if (m >= M3) return;
    float base = vt[m];
    u64 acc[16];
    u64 b0 = pk2(base, base);
    #pragma unroll
    for (int p = 0; p < 16; p++) acc[p] = b0;
    #pragma unroll 2
    for (int k = 0; k < NBb; k++) {
        float s = sds[k * 256 + tx];
        u64 sp = pk2(s, s);
        const ulonglong2* row = (const ulonglong2*)(bs2 + k * 16);
        #pragma unroll
        for (int h = 0; h < 8; h++) {
            ulonglong2 e = row[h];
            acc[2 * h + 0] = fma2(e.x, sp, acc[2 * h + 0]);
            acc[2 * h + 1] = fma2(e.y, sp, acc[2 * h + 1]);
        }
    }
    #pragma unroll
    for (int p = 0; p < 16; p++) {
        float lo, hi;
        upk2(acc[p], lo, hi);
        g_vshaped[(size_t)(n0 + 2 * p) * M3 + m] = lo;
        g_vshaped[(size_t)(n0 + 2 * p + 1) * M3 + m] = hi;
    }
}

// ---------------- K3: locals + chain compose, merged (8 bodies/block) ------
__device__ __forceinline__ void rodrigues(float t0, float t1, float t2, float R[9]) {
    float a0 = t0 + 1e-8f, a1 = t1 + 1e-8f, a2 = t2 + 1e-8f;
    float ang = sqrtf(a0 * a0 + a1 * a1 + a2 * a2);
    float inv = 1.f / ang;
    float r0 = t0 * inv, r1 = t1 * inv, r2 = t2 * inv;
    float s, c;
    sincosf(ang, &s, &c);
    float oc = 1.f - c;
    R[0] = c + oc * r0 * r0;       R[1] = oc * r0 * r1 - s * r2;  R[2] = oc * r0 * r2 + s * r1;
    R[3] = oc * r0 * r1 + s * r2;  R[4] = c + oc * r1 * r1;       R[5] = oc * r1 * r2 - s * r0;
    R[6] = oc * r0 * r2 - s * r1;  R[7] = oc * r1 * r2 + s * r0;  R[8] = c + oc * r2 * r2;
}

__global__ void __launch_bounds__(288) k_lc(const float* __restrict__ beta,
                                            const float* __restrict__ theta,
                                            const float* __restrict__ bls) {
    __shared__ float sL[8 * 396];
    __shared__ float sJ[8 * 99];
    int n0 = blockIdx.x * 8;
    int tx = threadIdx.x;
    if (tx < 264) {
        int b = tx / 33, i = tx - b * 33;
        int n = n0 + b;
        const float* bt = beta + n * NBb;
        float e[5];
        e[0] = 1.f;
        e[1] = expf(bls[n * 6 + 0]);
        e[2] = expf(bls[n * 6 + 1]);
        e[3] = expf(bls[n * 6 + 2]);
        e[4] = expf(bls[n * 6 + 3]);

        float Ji[3] = {g_Jt[i * 3 + 0], g_Jt[i * 3 + 1], g_Jt[i * 3 + 2]};
        #pragma unroll
        for (int k = 0; k < NBb; k++) {
            const float* s = g_SJ + k * 99 + i * 3;
            float bk = bt[k];
            Ji[0] = fmaf(bk, s[0], Ji[0]);
            Ji[1] = fmaf(bk, s[1], Ji[1]);
            Ji[2] = fmaf(bk, s[2], Ji[2]);
        }
        sJ[b * 99 + i * 3 + 0] = Ji[0];
        sJ[b * 99 + i * 3 + 1] = Ji[1];
        sJ[b * 99 + i * 3 + 2] = Ji[2];

        float R[9];
        rodrigues(theta[n * 105 + i * 3 + 0], theta[n * 105 + i * 3 + 1],
                  theta[n * 105 + i * 3 + 2], R);
        float* L = sL + b * 396 + i * 12;
        if (i == 0) {
            #pragma unroll
            for (int r = 0; r < 3; r++) {
                L[r * 4 + 0] = R[r * 3 + 0];
                L[r * 4 + 1] = R[r * 3 + 1];
                L[r * 4 + 2] = R[r * 3 + 2];
                L[r * 4 + 3] = Ji[r];
            }
        } else {
            int p = i - 1;
            float Jp[3] = {g_Jt[p * 3 + 0], g_Jt[p * 3 + 1], g_Jt[p * 3 + 2]};
            #pragma unroll
            for (int k = 0; k < NBb; k++) {
                const float* s = g_SJ + k * 99 + p * 3;
                float bk = bt[k];
                Jp[0] = fmaf(bk, s[0], Jp[0]);
                Jp[1] = fmaf(bk, s[1], Jp[1]);
                Jp[2] = fmaf(bk, s[2], Jp[2]);
            }
            float sic[3] = {e[c_sc[i * 3 + 0]], e[c_sc[i * 3 + 1]], e[c_sc[i * 3 + 2]]};
            float ipr[3] = {1.f / e[c_sc[p * 3 + 0]], 1.f / e[c_sc[p * 3 + 1]],
                            1.f / e[c_sc[p * 3 + 2]]};
            #pragma unroll
            for (int r = 0; r < 3; r++) {
                #pragma unroll
                for (int c = 0; c < 3; c++)
                    L[r * 4 + c] = R[r * 3 + c] * sic[c] * ipr[r];
                L[r * 4 + 3] = Ji[r] - Jp[r];
            }
        }
    }
    __syncthreads();
    // chain compose: 3 independent G-rows per body -> 24 active threads
    if (tx < 24) {
        int b = tx / 3, r = tx - b * 3;
        int n = n0 + b;
        int pr = n >> 1, lane = n & 1;
        float* out = g_A2f + (size_t)pr * 792 + lane;
        const float* Lb = sL + b * 396;
        const float* Jb = sJ + b * 99;
        float G[4];
        #pragma unroll
        for (int c = 0; c < 4; c++) G[c] = Lb[r * 4 + c];
        #pragma unroll 1
        for (int i = 0; i < NJj; i++) {
            if (i > 0) {
                const float* L = Lb + i * 12;
                float Gn[4];
                #pragma unroll
                for (int c = 0; c < 4; c++) {
                    float acc = (c == 3) ? G[3] : 0.f;
                    acc = fmaf(G[0], L[0 * 4 + c], acc);
                    acc = fmaf(G[1], L[1 * 4 + c], acc);
                    acc = fmaf(G[2], L[2 * 4 + c], acc);
                    Gn[c] = acc;
                }
                #pragma unroll
                for (int c = 0; c < 4; c++) G[c] = Gn[c];
            }
            float ib = G[0] * Jb[i * 3 + 0] + G[1] * Jb[i * 3 + 1] + G[2] * Jb[i * 3 + 2];
            out[(i * 12 + r * 4 + 0) * 2] = G[0];
            out[(i * 12 + r * 4 + 1) * 2] = G[1];
            out[(i * 12 + r * 4 + 2) * 2] = G[2];
            out[(i * 12 + r * 4 + 3) * 2] = G[3] - ib;
        }
    }
}

// ---------------- K4: skinning; 128 thr, 2 verts/thread, 16 bodies/block ---
__device__ __forceinline__ int eidx(int v) {
    if (v == 1863) return 0;
    if (v == 26)   return 1;
    if (v == 2124) return 2;
    if (v == 150)  return 3;
    if (v == 3055) return 4;
    if (v == 1097) return 5;
    return -1;
}

__global__ void __launch_bounds__(128) k_skin(const float* __restrict__ wts,
                                              const float* __restrict__ trans,
                                              float* __restrict__ outv,
                                              float* __restrict__ outj) {
    __shared__ __align__(16) float sw[256 * 33];
    __shared__ __align__(16) u64 As2[396];
    int chunk = blockIdx.x, n0 = blockIdx.y * 16;
    int v0 = chunk * 256;
    int tx = threadIdx.x;
    int cnt = min(256, Vv - v0);
    int wtot = cnt * 33;
    const u64* gA2 = (const u64*)g_A2f;
    for (int i = tx; i < 8448; i += 128) sw[i] = (i < wtot) ? wts[v0 * 33 + i] : 0.f;
    int va = v0 + tx, vb = va + 128;
    bool ga = tx < cnt, gb = tx + 128 < cnt;
    int ea = eidx(va), eb = eidx(vb);

    #pragma unroll 1
    for (int pair = 0; pair < 8; pair++) {
        int pr = (n0 >> 1) + pair;
        int b0 = 2 * pr, b1 = b0 + 1;
        __syncthreads();
        for (int i = tx; i < 396; i += 128) As2[i] = gA2[(size_t)pr * 396 + i];
        __syncthreads();

        u64 vax = 0, vay = 0, vaz = 0, vbx = 0, vby = 0, vbz = 0;
        if (ga) {
            const float* q0 = g_vshaped + (size_t)b0 * M3 + va * 3;
            const float* q1 = g_vshaped + (size_t)b1 * M3 + va * 3;
            vax = pk2(q0[0], q1[0]); vay = pk2(q0[1], q1[1]); vaz = pk2(q0[2], q1[2]);
        }
        if (gb) {
            const float* q0 = g_vshaped + (size_t)b0 * M3 + vb * 3;
            const float* q1 = g_vshaped + (size_t)b1 * M3 + vb * 3;
            vbx = pk2(q0[0], q1[0]); vby = pk2(q0[1], q1[1]); vbz = pk2(q0[2], q1[2]);
        }
        u64 accA[12], accB[12];
        #pragma unroll
        for (int q = 0; q < 12; q++) { accA[q] = 0ull; accB[q] = 0ull; }
        const ulonglong2* Ap = (const ulonglong2*)As2;
        #pragma unroll 3
        for (int j = 0; j < 33; j++) {
            float wa = sw[tx * 33 + j];
            float wb = sw[(tx + 128) * 33 + j];
            u64 wa2 = pk2(wa, wa), wb2 = pk2(wb, wb);
            #pragma unroll
            for (int r = 0; r < 3; r++) {
                ulonglong2 e0 = Ap[j * 6 + r * 2 + 0];
                ulonglong2 e1 = Ap[j * 6 + r * 2 + 1];
                accA[r * 4 + 0] = fma2(wa2, e0.x, accA[r * 4 + 0]);
                accA[r * 4 + 1] = fma2(wa2, e0.y, accA[r * 4 + 1]);
                accA[r * 4 + 2] = fma2(wa2, e1.x, accA[r * 4 + 2]);
                accA[r * 4 + 3] = fma2(wa2, e1.y, accA[r * 4 + 3]);
                accB[r * 4 + 0] = fma2(wb2, e0.x, accB[r * 4 + 0]);
                accB[r * 4 + 1] = fma2(wb2, e0.y, accB[r * 4 + 1]);
                accB[r * 4 + 2] = fma2(wb2, e1.x, accB[r * 4 + 2]);
                accB[r * 4 + 3] = fma2(wb2, e1.y, accB[r * 4 + 3]);
            }
        }
        u64 tr2[3];
        #pragma unroll
        for (int r = 0; r < 3; r++) tr2[r] = pk2(trans[b0 * 3 + r], trans[b1 * 3 + r]);
        #pragma unroll
        for (int r = 0; r < 3; r++) {
            u64 oA = fma2(accA[r * 4 + 0], vax,
                     fma2(accA[r * 4 + 1], vay,
                     fma2(accA[r * 4 + 2], vaz, add2(accA[r * 4 + 3], tr2[r]))));
            u64 oB = fma2(accB[r * 4 + 0], vbx,
                     fma2(accB[r * 4 + 1], vby,
                     fma2(accB[r * 4 + 2], vbz, add2(accB[r * 4 + 3], tr2[r]))));
            float lo, hi;
            if (ga) {
                upk2(oA, lo, hi);
                outv[(size_t)b0 * M3 + va * 3 + r] = lo;
                outv[(size_t)b1 * M3 + va * 3 + r] = hi;
                if (ea >= 0) {
                    outj[b0 * 117 + (33 + ea) * 3 + r] = lo;
                    outj[b1 * 117 + (33 + ea) * 3 + r] = hi;
                }
            }
            if (gb) {
                upk2(oB, lo, hi);
                outv[(size_t)b0 * M3 + vb * 3 + r] = lo;
                outv[(size_t)b1 * M3 + vb * 3 + r] = hi;
                if (eb >= 0) {
                    outj[b0 * 117 + (33 + eb) * 3 + r] = lo;
                    outj[b1 * 117 + (33 + eb) * 3 + r] = hi;
                }
            }
        }
    }
}

// ---------------- K5: joint partials; double-buffered, 1 sync/pair ---------
__global__ void __launch_bounds__(256) k_joints(const float* __restrict__ verts) {
    __shared__ __align__(16) float jrTs[NJj * 258];
    __shared__ __align__(16) float vsT[2][6 * 264];
    int chunk = blockIdx.x, n0 = blockIdx.y * 32;
    int v0 = chunk * 256;
    int tx = threadIdx.x;
    int cnt = min(256, Vv - v0);
    for (int i = tx; i < NJj * 256; i += 256) {
        int jj = i >> 8, v = i & 255;
        jrTs[jj * 258 + v] = (v < cnt) ? g_jrT[jj * JRW + v0 + v] : 0.f;
    }
    int g = tx / 99, q2 = tx - g * 99;
    int j = q2 / 3, a = q2 - j * 3;
    bool act = tx < 198;

    // stage pair 0 into buffer 0
    for (int i = tx; i < 1536; i += 256) {
        int b = i / 768, q = i - b * 768;
        int v = q / 3, aa = q - v * 3;
        vsT[0][(b * 3 + aa) * 264 + v] =
            (v < cnt) ? verts[(size_t)(n0 + b) * M3 + v0 * 3 + q] : 0.f;
    }
    __syncthreads();

    #pragma unroll 1
    for (int pair = 0; pair < 16; pair++) {
        int cur = pair & 1;
        // prefetch next pair into the other buffer
        if (pair < 15) {
            int b0n = n0 + 2 * (pair + 1);
            for (int i = tx; i < 1536; i += 256) {
                int b = i / 768, q = i - b * 768;
                int v = q / 3, aa = q - v * 3;
                vsT[1 - cur][(b * 3 + aa) * 264 + v] =
                    (v < cnt) ? verts[(size_t)(b0n + b) * M3 + v0 * 3 + q] : 0.f;
            }
        }
        if (act) {
            u64 acc0 = 0ull, acc1 = 0ull;
            const u64* jp = (const u64*)(jrTs + j * 258) + g * 64;
            const u64* p0 = (const u64*)(vsT[cur] + a * 264) + g * 64;
            const u64* p1 = (const u64*)(vsT[cur] + (3 + a) * 264) + g * 64;
            #pragma unroll 8
            for (int h = 0; h < 64; h++) {
                u64 jv = jp[h];
                acc0 = fma2(p0[h], jv, acc0);
                acc1 = fma2(p1[h], jv, acc1);
            }
            int b0 = n0 + 2 * pair;
            float lo, hi;
            upk2(acc0, lo, hi);
            g_jpart[((size_t)b0 * 32 + chunk * 2 + g) * 99 + q2] = lo + hi;
            upk2(acc1, lo, hi);
            g_jpart[((size_t)(b0 + 1) * 32 + chunk * 2 + g) * 99 + q2] = lo + hi;
        }
        __syncthreads();
    }
}

// ---------------- K6: deterministic joint reduce (32 fixed-order partials) -
__global__ void k_jred(float* __restrict__ outj) {
    int idx = blockIdx.x * 256 + threadIdx.x;
    if (idx >= Nn * 99) return;
    int n = idx / 99, t = idx - n * 99;
    const float* p = g_jpart + (size_t)n * 32 * 99 + t;
    float acc = 0.f;
    #pragma unroll
    for (int c = 0; c < 32; c++) acc += p[c * 99];
    outj[n * 117 + t] = acc;
}

// ---------------- launch: fork-join so vshape overlaps jrT->sj->lc ---------
extern "C" void kernel_launch(void* const* d_in, const int* in_sizes, int n_in,
                              void* d_out, int out_size) {
    const float* beta  = (const float*)d_in[0];
    const float* theta = (const float*)d_in[1];
    const float* trans = (const float*)d_in[2];
    const float* bls   = (const float*)d_in[3];
    const float* sd    = (const float*)d_in[4];
    const float* vt    = (const float*)d_in[5];
    const float* jreg  = (const float*)d_in[6];
    // d_in[7] = posedirs: multiplied by exact zeros in the reference -> unused
    const float* wts   = (const float*)d_in[8];
    float* outv = (float*)d_out;
    float* outj = outv + (size_t)Nn * M3;

    cudaStream_t s2;
    cudaStreamCreateWithFlags(&s2, cudaStreamNonBlocking);
    cudaEvent_t eFork, eJoin;
    cudaEventCreateWithFlags(&eFork, cudaEventDisableTiming);
    cudaEventCreateWithFlags(&eJoin, cudaEventDisableTiming);

    // fork: vshape on s2, concurrent with jrT -> sj -> lc on the main stream
    cudaEventRecord(eFork, 0);
    cudaStreamWaitEvent(s2, eFork, 0);
    k_vshape <<<dim3(46, 32), 256, 0, s2>>>(beta, sd, vt);
    cudaEventRecord(eJoin, s2);

    k_jrT    <<<dim3(16, 33), 256>>>(jreg);
    k_sj     <<<dim3(42, 33), 256>>>(sd, vt);
    k_lc     <<<128, 288>>>(beta, theta, bls);

    // join: skin needs both vshape and lc
    cudaStreamWaitEvent(0, eJoin, 0);
    k_skin   <<<dim3(16, 64), 128>>>(wts, trans, outv, outj);
    k_joints <<<dim3(16, 32), 256>>>(outv);
    k_jred   <<<(Nn * 99 + 255) / 256, 256>>>(outj);
}